// round 3
// baseline (speedup 1.0000x reference)
#include <cuda_runtime.h>
#include <cuda_bf16.h>

// Problem constants (fixed by the dataset)
#define NMAX 100000
#define EMAX 1600000
#define IN_D 128
#define OUT_D 32
#define NHEAD 4

// Scratch (allocation-free: __device__ globals)
__device__ float g_Wh[(size_t)NMAX * OUT_D];        // 12.8 MB
__device__ float g_asrc[(size_t)NMAX * NHEAD];      // 1.6 MB
__device__ float g_adst[(size_t)NMAX * NHEAD];      // 1.6 MB
__device__ float g_exp[(size_t)EMAX * NHEAD];       // 25.6 MB
__device__ float g_denom[(size_t)NMAX * NHEAD];     // 1.6 MB

__device__ __forceinline__ void red_add_v4(float* p, float4 v) {
    asm volatile("red.global.add.v4.f32 [%0], {%1,%2,%3,%4};"
                 :: "l"(p), "f"(v.x), "f"(v.y), "f"(v.z), "f"(v.w) : "memory");
}

// ---------------------------------------------------------------------------
// Kernel 0: zero out (d_out is poisoned) and denom
// ---------------------------------------------------------------------------
__global__ void __launch_bounds__(256) k_zero(float4* out4, int n4a, float4* den4, int n4b) {
    float4 z = make_float4(0.f, 0.f, 0.f, 0.f);
    int stride = gridDim.x * blockDim.x;
    for (int i = blockIdx.x * blockDim.x + threadIdx.x; i < n4a + n4b; i += stride) {
        if (i < n4a) out4[i] = z;
        else den4[i - n4a] = z;
    }
}

// ---------------------------------------------------------------------------
// Kernel 1: Wh = feat @ W^T + b  ;  a_src = Wh @ attS^T ; a_dst = Wh @ attD^T
// Block = 256 threads, 32 nodes/block. Thread (td = t&7, tn = t>>3) computes
// a 1-node x 4-dim register tile.  Smem: 16384 + 16896 + 1024 = 34304 B.
// ---------------------------------------------------------------------------
__global__ void __launch_bounds__(256) k_proj(
    const float* __restrict__ feat, const float* __restrict__ W,
    const float* __restrict__ bias, const float* __restrict__ attS,
    const float* __restrict__ attD, int N)
{
    __shared__ float sW[IN_D * OUT_D];     // transposed: sW[k*32+d]
    __shared__ float sF[32 * 132];         // padded row stride 132 floats
    __shared__ float sA[2 * NHEAD * OUT_D];

    int tid = threadIdx.x;
    int node0 = blockIdx.x * 32;

    // Load W transposed (coalesced global reads)
    #pragma unroll
    for (int i = 0; i < 16; i++) {
        int idx = tid + i * 256;            // idx = d*128 + k
        int d = idx >> 7, k = idx & 127;
        sW[k * 32 + d] = W[idx];
    }
    sA[tid] = (tid < 128) ? attS[tid] : attD[tid - 128];

    // Load 32 feature rows (float4, coalesced)
    const float4* f4 = reinterpret_cast<const float4*>(feat);
    #pragma unroll
    for (int i = 0; i < 4; i++) {
        int idx = tid + i * 256;            // 0..1023
        int n = idx >> 5, c = idx & 31;
        int gn = node0 + n;
        float4 v = (gn < N) ? f4[(size_t)gn * 32 + c] : make_float4(0.f, 0.f, 0.f, 0.f);
        *reinterpret_cast<float4*>(&sF[n * 132 + c * 4]) = v;
    }
    __syncthreads();

    int td = tid & 7, tn = tid >> 3;
    float acc[4];
    #pragma unroll
    for (int c = 0; c < 4; c++) acc[c] = __ldg(&bias[td * 4 + c]);

    #pragma unroll 4
    for (int k4 = 0; k4 < 32; k4++) {
        float4 w0 = *reinterpret_cast<float4*>(&sW[(k4 * 4 + 0) * 32 + td * 4]);
        float4 w1 = *reinterpret_cast<float4*>(&sW[(k4 * 4 + 1) * 32 + td * 4]);
        float4 w2 = *reinterpret_cast<float4*>(&sW[(k4 * 4 + 2) * 32 + td * 4]);
        float4 w3 = *reinterpret_cast<float4*>(&sW[(k4 * 4 + 3) * 32 + td * 4]);
        float4 f  = *reinterpret_cast<float4*>(&sF[tn * 132 + k4 * 4]);
        acc[0] += f.x * w0.x + f.y * w1.x + f.z * w2.x + f.w * w3.x;
        acc[1] += f.x * w0.y + f.y * w1.y + f.z * w2.y + f.w * w3.y;
        acc[2] += f.x * w0.z + f.y * w1.z + f.z * w2.z + f.w * w3.z;
        acc[3] += f.x * w0.w + f.y * w1.w + f.z * w2.w + f.w * w3.w;
    }

    int gn = node0 + tn;

    // Write Wh (float4, coalesced in 128B segments)
    if (gn < N) {
        *reinterpret_cast<float4*>(&g_Wh[(size_t)gn * 32 + td * 4]) =
            make_float4(acc[0], acc[1], acc[2], acc[3]);
    }

    // Fused attention projections, reduced across the 8 td-lanes per node
    #pragma unroll
    for (int h = 0; h < NHEAD; h++) {
        const float* as = &sA[h * 32 + td * 4];
        const float* ad = &sA[128 + h * 32 + td * 4];
        float ps = acc[0] * as[0] + acc[1] * as[1] + acc[2] * as[2] + acc[3] * as[3];
        float pd = acc[0] * ad[0] + acc[1] * ad[1] + acc[2] * ad[2] + acc[3] * ad[3];
        ps += __shfl_down_sync(0xffffffffu, ps, 4);
        ps += __shfl_down_sync(0xffffffffu, ps, 2);
        ps += __shfl_down_sync(0xffffffffu, ps, 1);
        pd += __shfl_down_sync(0xffffffffu, pd, 4);
        pd += __shfl_down_sync(0xffffffffu, pd, 2);
        pd += __shfl_down_sync(0xffffffffu, pd, 1);
        if (td == 0 && gn < N) {
            g_asrc[(size_t)gn * 4 + h] = ps;
            g_adst[(size_t)gn * 4 + h] = pd;
        }
    }
}

// ---------------------------------------------------------------------------
// Kernel 2: per-edge logits -> exp (global max cancels in the softmax; skip
// it — alpha differs only by the 1e-16 denominator eps, rel err ~1e-15),
// accumulate denom[src] via vector red.
// ---------------------------------------------------------------------------
__global__ void __launch_bounds__(256) k_edge_a(const int* __restrict__ ei, int E) {
    int e = blockIdx.x * 256 + threadIdx.x;
    if (e >= E) return;
    int s = __ldg(&ei[e]);
    int d = __ldg(&ei[E + e]);
    float4 as = *reinterpret_cast<const float4*>(&g_asrc[(size_t)s * 4]);
    float4 ad = *reinterpret_cast<const float4*>(&g_adst[(size_t)d * 4]);
    float4 ex;
    float v;
    v = as.x + ad.x; v = v > 0.f ? v : 0.2f * v; ex.x = __expf(v);
    v = as.y + ad.y; v = v > 0.f ? v : 0.2f * v; ex.y = __expf(v);
    v = as.z + ad.z; v = v > 0.f ? v : 0.2f * v; ex.z = __expf(v);
    v = as.w + ad.w; v = v > 0.f ? v : 0.2f * v; ex.w = __expf(v);
    *reinterpret_cast<float4*>(&g_exp[(size_t)e * 4]) = ex;
    red_add_v4(&g_denom[(size_t)s * 4], ex);
}

// ---------------------------------------------------------------------------
// Kernel 3: warp per edge. lane l: h = l>>3, q = l&7 covers out[dst][h][4q..4q+3].
// ---------------------------------------------------------------------------
__global__ void __launch_bounds__(256) k_edge_b(const int* __restrict__ ei,
                                               float* __restrict__ out, int E) {
    int warp = threadIdx.x >> 5;
    int lane = threadIdx.x & 31;
    int e = blockIdx.x * 8 + warp;
    if (e >= E) return;
    int s = __ldg(&ei[e]);
    int d = __ldg(&ei[E + e]);
    int h = lane >> 3, q = lane & 7;
    float ex  = __ldg(&g_exp[(size_t)e * 4 + h]);
    float den = __ldg(&g_denom[(size_t)s * 4 + h]);
    float alpha = ex / (den + 1e-16f);
    float4 w = __ldg(reinterpret_cast<const float4*>(&g_Wh[(size_t)s * 32 + q * 4]));
    float4 m = make_float4(w.x * alpha, w.y * alpha, w.z * alpha, w.w * alpha);
    red_add_v4(&out[(size_t)d * 128 + lane * 4], m);
}

// ---------------------------------------------------------------------------
extern "C" void kernel_launch(void* const* d_in, const int* in_sizes, int n_in,
                              void* d_out, int out_size) {
    const float* feat = (const float*)d_in[0];
    const float* W    = (const float*)d_in[1];
    const float* b    = (const float*)d_in[2];
    const float* attS = (const float*)d_in[3];
    const float* attD = (const float*)d_in[4];
    const int*   ei   = (const int*)d_in[5];
    float* out = (float*)d_out;

    int N = in_sizes[0] / IN_D;
    int E = in_sizes[5] / 2;

    // Resolve device-symbol addresses for the zero kernel (host-side, no alloc)
    float* denom_ptr = nullptr;
    cudaGetSymbolAddress((void**)&denom_ptr, g_denom);

    int n4_out = N * 32;      // N*128 floats / 4
    int n4_den = N;           // N*4 floats / 4
    k_zero<<<2048, 256>>>((float4*)out, n4_out, (float4*)denom_ptr, n4_den);

    int blocks_proj = (N + 31) / 32;
    k_proj<<<blocks_proj, 256>>>(feat, W, b, attS, attD, N);

    int blocks_a = (E + 255) / 256;
    k_edge_a<<<blocks_a, 256>>>(ei, E);

    int blocks_b = (E + 7) / 8;
    k_edge_b<<<blocks_b, 256>>>(ei, out, E);
}

// round 4
// speedup vs baseline: 1.5363x; 1.5363x over previous
#include <cuda_runtime.h>
#include <cuda_bf16.h>

// Problem constants (fixed by the dataset)
#define NMAX 100001
#define EMAX 1600000
#define IN_D 128
#define OUT_D 32
#define NHEAD 4

// Scratch (allocation-free: __device__ globals)
__device__ float g_Wh[(size_t)NMAX * OUT_D];
__device__ float g_asrc[(size_t)NMAX * NHEAD];
__device__ float g_adst[(size_t)NMAX * NHEAD];
__device__ float g_denom[(size_t)NMAX * NHEAD];
__device__ int   g_count[NMAX];
__device__ int   g_row[NMAX];
__device__ int   g_cursor[NMAX];
__device__ int   g_bsum[256];
__device__ int   g_csr_src[EMAX];
__device__ float g_csr_alpha[(size_t)EMAX * NHEAD];

__device__ __forceinline__ void red_add_v4(float* p, float4 v) {
    asm volatile("red.global.add.v4.f32 [%0], {%1,%2,%3,%4};"
                 :: "l"(p), "f"(v.x), "f"(v.y), "f"(v.z), "f"(v.w) : "memory");
}

// ---------------------------------------------------------------------------
// Kernel 0: zero denom + count (out no longer needs zeroing: gather writes all)
// ---------------------------------------------------------------------------
__global__ void __launch_bounds__(256) k_zero(int N) {
    int i = blockIdx.x * 256 + threadIdx.x;
    if (i < N) {
        *reinterpret_cast<float4*>(&g_denom[(size_t)i * 4]) = make_float4(0.f, 0.f, 0.f, 0.f);
        g_count[i] = 0;
    }
}

// ---------------------------------------------------------------------------
// Kernel 1: Wh = feat @ W^T + b ; a_src/a_dst projections
// ---------------------------------------------------------------------------
__global__ void __launch_bounds__(256) k_proj(
    const float* __restrict__ feat, const float* __restrict__ W,
    const float* __restrict__ bias, const float* __restrict__ attS,
    const float* __restrict__ attD, int N)
{
    __shared__ float sW[IN_D * OUT_D];     // transposed: sW[k*32+d]
    __shared__ float sF[32 * 132];         // padded row stride 132 floats
    __shared__ float sA[2 * NHEAD * OUT_D];

    int tid = threadIdx.x;
    int node0 = blockIdx.x * 32;

    #pragma unroll
    for (int i = 0; i < 16; i++) {
        int idx = tid + i * 256;            // idx = d*128 + k
        int d = idx >> 7, k = idx & 127;
        sW[k * 32 + d] = W[idx];
    }
    sA[tid] = (tid < 128) ? attS[tid] : attD[tid - 128];

    const float4* f4 = reinterpret_cast<const float4*>(feat);
    #pragma unroll
    for (int i = 0; i < 4; i++) {
        int idx = tid + i * 256;
        int n = idx >> 5, c = idx & 31;
        int gn = node0 + n;
        float4 v = (gn < N) ? f4[(size_t)gn * 32 + c] : make_float4(0.f, 0.f, 0.f, 0.f);
        *reinterpret_cast<float4*>(&sF[n * 132 + c * 4]) = v;
    }
    __syncthreads();

    int td = tid & 7, tn = tid >> 3;
    float acc[4];
    #pragma unroll
    for (int c = 0; c < 4; c++) acc[c] = __ldg(&bias[td * 4 + c]);

    #pragma unroll 4
    for (int k4 = 0; k4 < 32; k4++) {
        float4 w0 = *reinterpret_cast<float4*>(&sW[(k4 * 4 + 0) * 32 + td * 4]);
        float4 w1 = *reinterpret_cast<float4*>(&sW[(k4 * 4 + 1) * 32 + td * 4]);
        float4 w2 = *reinterpret_cast<float4*>(&sW[(k4 * 4 + 2) * 32 + td * 4]);
        float4 w3 = *reinterpret_cast<float4*>(&sW[(k4 * 4 + 3) * 32 + td * 4]);
        float4 f  = *reinterpret_cast<float4*>(&sF[tn * 132 + k4 * 4]);
        acc[0] += f.x * w0.x + f.y * w1.x + f.z * w2.x + f.w * w3.x;
        acc[1] += f.x * w0.y + f.y * w1.y + f.z * w2.y + f.w * w3.y;
        acc[2] += f.x * w0.z + f.y * w1.z + f.z * w2.z + f.w * w3.z;
        acc[3] += f.x * w0.w + f.y * w1.w + f.z * w2.w + f.w * w3.w;
    }

    int gn = node0 + tn;
    if (gn < N) {
        *reinterpret_cast<float4*>(&g_Wh[(size_t)gn * 32 + td * 4]) =
            make_float4(acc[0], acc[1], acc[2], acc[3]);
    }

    #pragma unroll
    for (int h = 0; h < NHEAD; h++) {
        const float* as = &sA[h * 32 + td * 4];
        const float* ad = &sA[128 + h * 32 + td * 4];
        float ps = acc[0] * as[0] + acc[1] * as[1] + acc[2] * as[2] + acc[3] * as[3];
        float pd = acc[0] * ad[0] + acc[1] * ad[1] + acc[2] * ad[2] + acc[3] * ad[3];
        ps += __shfl_down_sync(0xffffffffu, ps, 4);
        ps += __shfl_down_sync(0xffffffffu, ps, 2);
        ps += __shfl_down_sync(0xffffffffu, ps, 1);
        pd += __shfl_down_sync(0xffffffffu, pd, 4);
        pd += __shfl_down_sync(0xffffffffu, pd, 2);
        pd += __shfl_down_sync(0xffffffffu, pd, 1);
        if (td == 0 && gn < N) {
            g_asrc[(size_t)gn * 4 + h] = ps;
            g_adst[(size_t)gn * 4 + h] = pd;
        }
    }
}

// ---------------------------------------------------------------------------
// helper: leaky-relu + exp for 4 heads (global max cancels in softmax; skip)
// ---------------------------------------------------------------------------
__device__ __forceinline__ float4 edge_exp4(int s, int d) {
    float4 as = *reinterpret_cast<const float4*>(&g_asrc[(size_t)s * 4]);
    float4 ad = *reinterpret_cast<const float4*>(&g_adst[(size_t)d * 4]);
    float4 ex; float v;
    v = as.x + ad.x; v = v > 0.f ? v : 0.2f * v; ex.x = __expf(v);
    v = as.y + ad.y; v = v > 0.f ? v : 0.2f * v; ex.y = __expf(v);
    v = as.z + ad.z; v = v > 0.f ? v : 0.2f * v; ex.z = __expf(v);
    v = as.w + ad.w; v = v > 0.f ? v : 0.2f * v; ex.w = __expf(v);
    return ex;
}

// ---------------------------------------------------------------------------
// Kernel 2: denom[src] += exp(e)  and  count[dst]++ (fused histogram)
// ---------------------------------------------------------------------------
__global__ void __launch_bounds__(256) k_edge_a(const int* __restrict__ ei, int E) {
    int e = blockIdx.x * 256 + threadIdx.x;
    if (e >= E) return;
    int s = __ldg(&ei[e]);
    int d = __ldg(&ei[E + e]);
    float4 ex = edge_exp4(s, d);
    red_add_v4(&g_denom[(size_t)s * 4], ex);
    atomicAdd(&g_count[d], 1);
}

// ---------------------------------------------------------------------------
// Scan: exclusive prefix sum of count -> row (3 small kernels)
// ---------------------------------------------------------------------------
__global__ void __launch_bounds__(1024) k_scan_a(int N) {
    __shared__ int warp_sums[32];
    int b = blockIdx.x, t = threadIdx.x;
    int idx = b * 1024 + t;
    int v = (idx < N) ? g_count[idx] : 0;
    int lane = t & 31, w = t >> 5;
    int x = v;
    #pragma unroll
    for (int o = 1; o < 32; o <<= 1) {
        int y = __shfl_up_sync(0xffffffffu, x, o);
        if (lane >= o) x += y;
    }
    if (lane == 31) warp_sums[w] = x;
    __syncthreads();
    if (w == 0) {
        int s = warp_sums[lane];
        #pragma unroll
        for (int o = 1; o < 32; o <<= 1) {
            int y = __shfl_up_sync(0xffffffffu, s, o);
            if (lane >= o) s += y;
        }
        warp_sums[lane] = s;
    }
    __syncthreads();
    int warp_off = (w > 0) ? warp_sums[w - 1] : 0;
    if (idx < N) g_row[idx] = warp_off + x - v;   // exclusive
    if (t == 0) g_bsum[b] = warp_sums[31];        // block total
}

__global__ void __launch_bounds__(256) k_scan_b(int NB) {
    __shared__ int s[256];
    int t = threadIdx.x;
    s[t] = (t < NB) ? g_bsum[t] : 0;
    __syncthreads();
    #pragma unroll
    for (int o = 1; o < 256; o <<= 1) {
        int v = (t >= o) ? s[t - o] : 0;
        __syncthreads();
        s[t] += v;
        __syncthreads();
    }
    if (t < NB) g_bsum[t] = s[t];                 // inclusive
}

__global__ void __launch_bounds__(1024) k_scan_c(int N) {
    int idx = blockIdx.x * 1024 + threadIdx.x;
    if (idx >= N) return;
    int b = idx >> 10;
    int off = (b > 0) ? g_bsum[b - 1] : 0;
    int r = g_row[idx] + off;
    g_row[idx] = r;
    g_cursor[idx] = r;
}

// ---------------------------------------------------------------------------
// Kernel 3: scatter {src, alpha4} into CSR slots (recompute exp; denom ready)
// ---------------------------------------------------------------------------
__global__ void __launch_bounds__(256) k_scatter(const int* __restrict__ ei, int E) {
    int e = blockIdx.x * 256 + threadIdx.x;
    if (e >= E) return;
    int s = __ldg(&ei[e]);
    int d = __ldg(&ei[E + e]);
    float4 ex = edge_exp4(s, d);
    float4 den = *reinterpret_cast<const float4*>(&g_denom[(size_t)s * 4]);
    float4 al = make_float4(ex.x / (den.x + 1e-16f), ex.y / (den.y + 1e-16f),
                            ex.z / (den.z + 1e-16f), ex.w / (den.w + 1e-16f));
    int pos = atomicAdd(&g_cursor[d], 1);
    g_csr_src[pos] = s;
    *reinterpret_cast<float4*>(&g_csr_alpha[(size_t)pos * 4]) = al;
}

// ---------------------------------------------------------------------------
// Kernel 4: gather — warp per dst node, register accumulation, one store.
// lane l: h = l>>3, q = l&7 owns out[node][h*32 + 4q .. 4q+3].
// ---------------------------------------------------------------------------
__global__ void __launch_bounds__(256) k_gather(float* __restrict__ out, int N) {
    int warp = threadIdx.x >> 5;
    int lane = threadIdx.x & 31;
    int node = blockIdx.x * 8 + warp;
    if (node >= N) return;
    int start = __ldg(&g_row[node]);
    int cnt   = __ldg(&g_count[node]);
    int h = lane >> 3, q = lane & 7;

    float4 acc = make_float4(0.f, 0.f, 0.f, 0.f);
    int i = 0;
    for (; i + 4 <= cnt; i += 4) {
        int p = start + i;
        int s0 = __ldg(&g_csr_src[p + 0]);
        int s1 = __ldg(&g_csr_src[p + 1]);
        int s2 = __ldg(&g_csr_src[p + 2]);
        int s3 = __ldg(&g_csr_src[p + 3]);
        float a0 = __ldg(&g_csr_alpha[(size_t)(p + 0) * 4 + h]);
        float a1 = __ldg(&g_csr_alpha[(size_t)(p + 1) * 4 + h]);
        float a2 = __ldg(&g_csr_alpha[(size_t)(p + 2) * 4 + h]);
        float a3 = __ldg(&g_csr_alpha[(size_t)(p + 3) * 4 + h]);
        float4 w0 = __ldg(reinterpret_cast<const float4*>(&g_Wh[(size_t)s0 * 32 + q * 4]));
        float4 w1 = __ldg(reinterpret_cast<const float4*>(&g_Wh[(size_t)s1 * 32 + q * 4]));
        float4 w2 = __ldg(reinterpret_cast<const float4*>(&g_Wh[(size_t)s2 * 32 + q * 4]));
        float4 w3 = __ldg(reinterpret_cast<const float4*>(&g_Wh[(size_t)s3 * 32 + q * 4]));
        acc.x += a0 * w0.x + a1 * w1.x + a2 * w2.x + a3 * w3.x;
        acc.y += a0 * w0.y + a1 * w1.y + a2 * w2.y + a3 * w3.y;
        acc.z += a0 * w0.z + a1 * w1.z + a2 * w2.z + a3 * w3.z;
        acc.w += a0 * w0.w + a1 * w1.w + a2 * w2.w + a3 * w3.w;
    }
    for (; i < cnt; i++) {
        int p = start + i;
        int s0 = __ldg(&g_csr_src[p]);
        float a0 = __ldg(&g_csr_alpha[(size_t)p * 4 + h]);
        float4 w0 = __ldg(reinterpret_cast<const float4*>(&g_Wh[(size_t)s0 * 32 + q * 4]));
        acc.x += a0 * w0.x; acc.y += a0 * w0.y; acc.z += a0 * w0.z; acc.w += a0 * w0.w;
    }
    *reinterpret_cast<float4*>(&out[(size_t)node * 128 + lane * 4]) = acc;
}

// ---------------------------------------------------------------------------
extern "C" void kernel_launch(void* const* d_in, const int* in_sizes, int n_in,
                              void* d_out, int out_size) {
    const float* feat = (const float*)d_in[0];
    const float* W    = (const float*)d_in[1];
    const float* b    = (const float*)d_in[2];
    const float* attS = (const float*)d_in[3];
    const float* attD = (const float*)d_in[4];
    const int*   ei   = (const int*)d_in[5];
    float* out = (float*)d_out;

    int N = in_sizes[0] / IN_D;
    int E = in_sizes[5] / 2;

    k_zero<<<(N + 255) / 256, 256>>>(N);
    k_proj<<<(N + 31) / 32, 256>>>(feat, W, b, attS, attD, N);
    k_edge_a<<<(E + 255) / 256, 256>>>(ei, E);

    int NB = (N + 1023) / 1024;     // <= 256 for N <= 262144
    k_scan_a<<<NB, 1024>>>(N);
    k_scan_b<<<1, 256>>>(NB);
    k_scan_c<<<NB, 1024>>>(N);

    k_scatter<<<(E + 255) / 256, 256>>>(ei, E);
    k_gather<<<(N + 7) / 8, 256>>>(out, N);
}

// round 5
// speedup vs baseline: 1.5455x; 1.0060x over previous
#include <cuda_runtime.h>
#include <cuda_bf16.h>

// Problem constants (fixed by the dataset)
#define NMAX 100001
#define EMAX 1600000
#define IN_D 128
#define OUT_D 32
#define NHEAD 4

// Scratch (allocation-free: __device__ globals)
__device__ float g_Wh[(size_t)NMAX * OUT_D];
__device__ float g_asrc[(size_t)NMAX * NHEAD];
__device__ float g_adst[(size_t)NMAX * NHEAD];
__device__ float g_denom[(size_t)NMAX * NHEAD];     // later overwritten with 1/(denom+eps)
__device__ int   g_count[NMAX];
__device__ int   g_row[NMAX];
__device__ int   g_cursor[NMAX];
__device__ int   g_bsum[256];
__device__ int   g_csr_src[EMAX];
__device__ float g_csr_ex[(size_t)EMAX * NHEAD];    // un-normalized exp(e) per head

__device__ __forceinline__ void red_add_v4(float* p, float4 v) {
    asm volatile("red.global.add.v4.f32 [%0], {%1,%2,%3,%4};"
                 :: "l"(p), "f"(v.x), "f"(v.y), "f"(v.z), "f"(v.w) : "memory");
}

// ---------------------------------------------------------------------------
// Kernel 0: zero denom + count
// ---------------------------------------------------------------------------
__global__ void __launch_bounds__(256) k_zero(int N) {
    int i = blockIdx.x * 256 + threadIdx.x;
    if (i < N) {
        *reinterpret_cast<float4*>(&g_denom[(size_t)i * 4]) = make_float4(0.f, 0.f, 0.f, 0.f);
        g_count[i] = 0;
    }
}

// ---------------------------------------------------------------------------
// Kernel 1: Wh = feat @ W^T + b ; a_src/a_dst projections
// ---------------------------------------------------------------------------
__global__ void __launch_bounds__(256) k_proj(
    const float* __restrict__ feat, const float* __restrict__ W,
    const float* __restrict__ bias, const float* __restrict__ attS,
    const float* __restrict__ attD, int N)
{
    __shared__ float sW[IN_D * OUT_D];     // transposed: sW[k*32+d]
    __shared__ float sF[32 * 132];         // padded row stride 132 floats
    __shared__ float sA[2 * NHEAD * OUT_D];

    int tid = threadIdx.x;
    int node0 = blockIdx.x * 32;

    #pragma unroll
    for (int i = 0; i < 16; i++) {
        int idx = tid + i * 256;            // idx = d*128 + k
        int d = idx >> 7, k = idx & 127;
        sW[k * 32 + d] = W[idx];
    }
    sA[tid] = (tid < 128) ? attS[tid] : attD[tid - 128];

    const float4* f4 = reinterpret_cast<const float4*>(feat);
    #pragma unroll
    for (int i = 0; i < 4; i++) {
        int idx = tid + i * 256;
        int n = idx >> 5, c = idx & 31;
        int gn = node0 + n;
        float4 v = (gn < N) ? f4[(size_t)gn * 32 + c] : make_float4(0.f, 0.f, 0.f, 0.f);
        *reinterpret_cast<float4*>(&sF[n * 132 + c * 4]) = v;
    }
    __syncthreads();

    int td = tid & 7, tn = tid >> 3;
    float acc[4];
    #pragma unroll
    for (int c = 0; c < 4; c++) acc[c] = __ldg(&bias[td * 4 + c]);

    #pragma unroll 4
    for (int k4 = 0; k4 < 32; k4++) {
        float4 w0 = *reinterpret_cast<float4*>(&sW[(k4 * 4 + 0) * 32 + td * 4]);
        float4 w1 = *reinterpret_cast<float4*>(&sW[(k4 * 4 + 1) * 32 + td * 4]);
        float4 w2 = *reinterpret_cast<float4*>(&sW[(k4 * 4 + 2) * 32 + td * 4]);
        float4 w3 = *reinterpret_cast<float4*>(&sW[(k4 * 4 + 3) * 32 + td * 4]);
        float4 f  = *reinterpret_cast<float4*>(&sF[tn * 132 + k4 * 4]);
        acc[0] += f.x * w0.x + f.y * w1.x + f.z * w2.x + f.w * w3.x;
        acc[1] += f.x * w0.y + f.y * w1.y + f.z * w2.y + f.w * w3.y;
        acc[2] += f.x * w0.z + f.y * w1.z + f.z * w2.z + f.w * w3.z;
        acc[3] += f.x * w0.w + f.y * w1.w + f.z * w2.w + f.w * w3.w;
    }

    int gn = node0 + tn;
    if (gn < N) {
        *reinterpret_cast<float4*>(&g_Wh[(size_t)gn * 32 + td * 4]) =
            make_float4(acc[0], acc[1], acc[2], acc[3]);
    }

    #pragma unroll
    for (int h = 0; h < NHEAD; h++) {
        const float* as = &sA[h * 32 + td * 4];
        const float* ad = &sA[128 + h * 32 + td * 4];
        float ps = acc[0] * as[0] + acc[1] * as[1] + acc[2] * as[2] + acc[3] * as[3];
        float pd = acc[0] * ad[0] + acc[1] * ad[1] + acc[2] * ad[2] + acc[3] * ad[3];
        ps += __shfl_down_sync(0xffffffffu, ps, 4);
        ps += __shfl_down_sync(0xffffffffu, ps, 2);
        ps += __shfl_down_sync(0xffffffffu, ps, 1);
        pd += __shfl_down_sync(0xffffffffu, pd, 4);
        pd += __shfl_down_sync(0xffffffffu, pd, 2);
        pd += __shfl_down_sync(0xffffffffu, pd, 1);
        if (td == 0 && gn < N) {
            g_asrc[(size_t)gn * 4 + h] = ps;
            g_adst[(size_t)gn * 4 + h] = pd;
        }
    }
}

// ---------------------------------------------------------------------------
// Kernel 2: histogram of dst only (cheap: 6.4 MB read + L2 atomics)
// ---------------------------------------------------------------------------
__global__ void __launch_bounds__(256) k_hist(const int* __restrict__ dst, int E) {
    int e = blockIdx.x * 256 + threadIdx.x;
    if (e < E) atomicAdd(&g_count[__ldg(&dst[e])], 1);
}

// ---------------------------------------------------------------------------
// Scan: exclusive prefix sum of count -> row (3 small kernels)
// ---------------------------------------------------------------------------
__global__ void __launch_bounds__(1024) k_scan_a(int N) {
    __shared__ int warp_sums[32];
    int b = blockIdx.x, t = threadIdx.x;
    int idx = b * 1024 + t;
    int v = (idx < N) ? g_count[idx] : 0;
    int lane = t & 31, w = t >> 5;
    int x = v;
    #pragma unroll
    for (int o = 1; o < 32; o <<= 1) {
        int y = __shfl_up_sync(0xffffffffu, x, o);
        if (lane >= o) x += y;
    }
    if (lane == 31) warp_sums[w] = x;
    __syncthreads();
    if (w == 0) {
        int s = warp_sums[lane];
        #pragma unroll
        for (int o = 1; o < 32; o <<= 1) {
            int y = __shfl_up_sync(0xffffffffu, s, o);
            if (lane >= o) s += y;
        }
        warp_sums[lane] = s;
    }
    __syncthreads();
    int warp_off = (w > 0) ? warp_sums[w - 1] : 0;
    if (idx < N) g_row[idx] = warp_off + x - v;   // exclusive
    if (t == 0) g_bsum[b] = warp_sums[31];        // block total
}

__global__ void __launch_bounds__(256) k_scan_b(int NB) {
    __shared__ int s[256];
    int t = threadIdx.x;
    s[t] = (t < NB) ? g_bsum[t] : 0;
    __syncthreads();
    #pragma unroll
    for (int o = 1; o < 256; o <<= 1) {
        int v = (t >= o) ? s[t - o] : 0;
        __syncthreads();
        s[t] += v;
        __syncthreads();
    }
    if (t < NB) g_bsum[t] = s[t];                 // inclusive
}

__global__ void __launch_bounds__(1024) k_scan_c(int N) {
    int idx = blockIdx.x * 1024 + threadIdx.x;
    if (idx >= N) return;
    int b = idx >> 10;
    int off = (b > 0) ? g_bsum[b - 1] : 0;
    int r = g_row[idx] + off;
    g_row[idx] = r;
    g_cursor[idx] = r;
}

// ---------------------------------------------------------------------------
// Kernel 3 (fused): per-edge exp, denom[src] reduction, and CSR scatter of the
// RAW exponentials. Normalization moves to the gather via rdenom.
// ---------------------------------------------------------------------------
__global__ void __launch_bounds__(256) k_edge_fused(const int* __restrict__ ei, int E) {
    int e = blockIdx.x * 256 + threadIdx.x;
    if (e >= E) return;
    int s = __ldg(&ei[e]);
    int d = __ldg(&ei[E + e]);
    float4 as = *reinterpret_cast<const float4*>(&g_asrc[(size_t)s * 4]);
    float4 ad = *reinterpret_cast<const float4*>(&g_adst[(size_t)d * 4]);
    float4 ex; float v;
    v = as.x + ad.x; v = v > 0.f ? v : 0.2f * v; ex.x = __expf(v);
    v = as.y + ad.y; v = v > 0.f ? v : 0.2f * v; ex.y = __expf(v);
    v = as.z + ad.z; v = v > 0.f ? v : 0.2f * v; ex.z = __expf(v);
    v = as.w + ad.w; v = v > 0.f ? v : 0.2f * v; ex.w = __expf(v);
    red_add_v4(&g_denom[(size_t)s * 4], ex);
    int pos = atomicAdd(&g_cursor[d], 1);
    g_csr_src[pos] = s;
    *reinterpret_cast<float4*>(&g_csr_ex[(size_t)pos * 4]) = ex;
}

// ---------------------------------------------------------------------------
// Kernel 4: denom -> 1/(denom + eps) in place
// ---------------------------------------------------------------------------
__global__ void __launch_bounds__(256) k_rcp(int N) {
    int i = blockIdx.x * 256 + threadIdx.x;
    if (i >= N) return;
    float4 d = *reinterpret_cast<float4*>(&g_denom[(size_t)i * 4]);
    d.x = 1.f / (d.x + 1e-16f);
    d.y = 1.f / (d.y + 1e-16f);
    d.z = 1.f / (d.z + 1e-16f);
    d.w = 1.f / (d.w + 1e-16f);
    *reinterpret_cast<float4*>(&g_denom[(size_t)i * 4]) = d;
}

// ---------------------------------------------------------------------------
// Kernel 5: gather — warp per dst node, register accumulation, one store.
// lane l: h = l>>3, q = l&7 owns out[node][h*32 + 4q .. 4q+3].
// alpha = ex * rdenom[src]  (rdenom broadcast across the 8 lanes of a head)
// ---------------------------------------------------------------------------
__global__ void __launch_bounds__(256) k_gather(float* __restrict__ out, int N) {
    int warp = threadIdx.x >> 5;
    int lane = threadIdx.x & 31;
    int node = blockIdx.x * 8 + warp;
    if (node >= N) return;
    int start = __ldg(&g_row[node]);
    int cnt   = __ldg(&g_count[node]);
    int h = lane >> 3, q = lane & 7;

    float4 acc = make_float4(0.f, 0.f, 0.f, 0.f);
    int i = 0;
    for (; i + 4 <= cnt; i += 4) {
        int p = start + i;
        int s0 = __ldg(&g_csr_src[p + 0]);
        int s1 = __ldg(&g_csr_src[p + 1]);
        int s2 = __ldg(&g_csr_src[p + 2]);
        int s3 = __ldg(&g_csr_src[p + 3]);
        float a0 = __ldg(&g_csr_ex[(size_t)(p + 0) * 4 + h]) * __ldg(&g_denom[(size_t)s0 * 4 + h]);
        float a1 = __ldg(&g_csr_ex[(size_t)(p + 1) * 4 + h]) * __ldg(&g_denom[(size_t)s1 * 4 + h]);
        float a2 = __ldg(&g_csr_ex[(size_t)(p + 2) * 4 + h]) * __ldg(&g_denom[(size_t)s2 * 4 + h]);
        float a3 = __ldg(&g_csr_ex[(size_t)(p + 3) * 4 + h]) * __ldg(&g_denom[(size_t)s3 * 4 + h]);
        float4 w0 = __ldg(reinterpret_cast<const float4*>(&g_Wh[(size_t)s0 * 32 + q * 4]));
        float4 w1 = __ldg(reinterpret_cast<const float4*>(&g_Wh[(size_t)s1 * 32 + q * 4]));
        float4 w2 = __ldg(reinterpret_cast<const float4*>(&g_Wh[(size_t)s2 * 32 + q * 4]));
        float4 w3 = __ldg(reinterpret_cast<const float4*>(&g_Wh[(size_t)s3 * 32 + q * 4]));
        acc.x += a0 * w0.x + a1 * w1.x + a2 * w2.x + a3 * w3.x;
        acc.y += a0 * w0.y + a1 * w1.y + a2 * w2.y + a3 * w3.y;
        acc.z += a0 * w0.z + a1 * w1.z + a2 * w2.z + a3 * w3.z;
        acc.w += a0 * w0.w + a1 * w1.w + a2 * w2.w + a3 * w3.w;
    }
    for (; i < cnt; i++) {
        int p = start + i;
        int s0 = __ldg(&g_csr_src[p]);
        float a0 = __ldg(&g_csr_ex[(size_t)p * 4 + h]) * __ldg(&g_denom[(size_t)s0 * 4 + h]);
        float4 w0 = __ldg(reinterpret_cast<const float4*>(&g_Wh[(size_t)s0 * 32 + q * 4]));
        acc.x += a0 * w0.x; acc.y += a0 * w0.y; acc.z += a0 * w0.z; acc.w += a0 * w0.w;
    }
    *reinterpret_cast<float4*>(&out[(size_t)node * 128 + lane * 4]) = acc;
}

// ---------------------------------------------------------------------------
extern "C" void kernel_launch(void* const* d_in, const int* in_sizes, int n_in,
                              void* d_out, int out_size) {
    const float* feat = (const float*)d_in[0];
    const float* W    = (const float*)d_in[1];
    const float* b    = (const float*)d_in[2];
    const float* attS = (const float*)d_in[3];
    const float* attD = (const float*)d_in[4];
    const int*   ei   = (const int*)d_in[5];
    float* out = (float*)d_out;

    int N = in_sizes[0] / IN_D;
    int E = in_sizes[5] / 2;

    k_zero<<<(N + 255) / 256, 256>>>(N);
    k_hist<<<(E + 255) / 256, 256>>>(ei + E, E);
    k_proj<<<(N + 31) / 32, 256>>>(feat, W, b, attS, attD, N);

    int NB = (N + 1023) / 1024;     // <= 256 for N <= 262144
    k_scan_a<<<NB, 1024>>>(N);
    k_scan_b<<<1, 256>>>(NB);
    k_scan_c<<<NB, 1024>>>(N);

    k_edge_fused<<<(E + 255) / 256, 256>>>(ei, E);
    k_rcp<<<(N + 255) / 256, 256>>>(N);
    k_gather<<<(N + 7) / 8, 256>>>(out, N);
}

// round 7
// speedup vs baseline: 1.7662x; 1.1428x over previous
#include <cuda_runtime.h>
#include <cuda_bf16.h>

// Problem constants (fixed by the dataset)
#define NMAX 100001
#define EMAX 1600000
#define IN_D 128
#define OUT_D 32
#define NHEAD 4

struct __align__(32) Rec { float4 a; float4 b; };   // a = {src, ex0, ex1, ex2}, b.x = ex3

// Scratch (allocation-free: __device__ globals)
__device__ float g_Wh[(size_t)NMAX * OUT_D];
__device__ float g_asrc[(size_t)NMAX * NHEAD];
__device__ float g_adst[(size_t)NMAX * NHEAD];
__device__ float g_denom[(size_t)NMAX * NHEAD];     // later overwritten with 1/(denom+eps)
__device__ int   g_count[NMAX];
__device__ int   g_row[NMAX];
__device__ int   g_cursor[NMAX];
__device__ int   g_bsum[256];
__device__ Rec   g_csr[EMAX];                       // 51.2 MB packed records

__device__ __forceinline__ void red_add_v4(float* p, float4 v) {
    asm volatile("red.global.add.v4.f32 [%0], {%1,%2,%3,%4};"
                 :: "l"(p), "f"(v.x), "f"(v.y), "f"(v.z), "f"(v.w) : "memory");
}

// ---------------------------------------------------------------------------
// Kernel 0: zero denom + count
// ---------------------------------------------------------------------------
__global__ void __launch_bounds__(256) k_zero(int N) {
    int i = blockIdx.x * 256 + threadIdx.x;
    if (i < N) {
        *reinterpret_cast<float4*>(&g_denom[(size_t)i * 4]) = make_float4(0.f, 0.f, 0.f, 0.f);
        g_count[i] = 0;
    }
}

// ---------------------------------------------------------------------------
// Kernel 1: Wh = feat @ W^T + b ; a_src/a_dst projections
// 128 threads, 32 nodes/block, 2 nodes per thread (td = t&7, tn = t>>3).
// Smem: 16384 + 16896 + 1024 = 34304 B.
// ---------------------------------------------------------------------------
__global__ void __launch_bounds__(128) k_proj(
    const float* __restrict__ feat, const float* __restrict__ W,
    const float* __restrict__ bias, const float* __restrict__ attS,
    const float* __restrict__ attD, int N)
{
    __shared__ float sW[IN_D * OUT_D];     // transposed: sW[k*32+d]
    __shared__ float sF[32 * 132];         // padded row stride 132 floats
    __shared__ float sA[2 * NHEAD * OUT_D];

    int tid = threadIdx.x;
    int node0 = blockIdx.x * 32;

    #pragma unroll
    for (int i = 0; i < 32; i++) {
        int idx = tid + i * 128;            // idx = d*128 + k
        int d = idx >> 7, k = idx & 127;
        sW[k * 32 + d] = W[idx];
    }
    sA[tid] = attS[tid];
    sA[tid + 128] = attD[tid];

    const float4* f4 = reinterpret_cast<const float4*>(feat);
    #pragma unroll
    for (int i = 0; i < 8; i++) {
        int idx = tid + i * 128;            // 0..1023
        int n = idx >> 5, c = idx & 31;
        int gn = node0 + n;
        float4 v = (gn < N) ? f4[(size_t)gn * 32 + c] : make_float4(0.f, 0.f, 0.f, 0.f);
        *reinterpret_cast<float4*>(&sF[n * 132 + c * 4]) = v;
    }
    __syncthreads();

    int td = tid & 7, tn = tid >> 3;        // tn in [0,16): nodes 2tn, 2tn+1
    float acc[2][4];
    #pragma unroll
    for (int c = 0; c < 4; c++) {
        float bb = __ldg(&bias[td * 4 + c]);
        acc[0][c] = bb; acc[1][c] = bb;
    }

    #pragma unroll 4
    for (int k4 = 0; k4 < 32; k4++) {
        float4 w0 = *reinterpret_cast<float4*>(&sW[(k4 * 4 + 0) * 32 + td * 4]);
        float4 w1 = *reinterpret_cast<float4*>(&sW[(k4 * 4 + 1) * 32 + td * 4]);
        float4 w2 = *reinterpret_cast<float4*>(&sW[(k4 * 4 + 2) * 32 + td * 4]);
        float4 w3 = *reinterpret_cast<float4*>(&sW[(k4 * 4 + 3) * 32 + td * 4]);
        #pragma unroll
        for (int j = 0; j < 2; j++) {
            float4 f = *reinterpret_cast<float4*>(&sF[(tn * 2 + j) * 132 + k4 * 4]);
            acc[j][0] += f.x * w0.x + f.y * w1.x + f.z * w2.x + f.w * w3.x;
            acc[j][1] += f.x * w0.y + f.y * w1.y + f.z * w2.y + f.w * w3.y;
            acc[j][2] += f.x * w0.z + f.y * w1.z + f.z * w2.z + f.w * w3.z;
            acc[j][3] += f.x * w0.w + f.y * w1.w + f.z * w2.w + f.w * w3.w;
        }
    }

    #pragma unroll
    for (int j = 0; j < 2; j++) {
        int gn = node0 + tn * 2 + j;
        if (gn < N) {
            *reinterpret_cast<float4*>(&g_Wh[(size_t)gn * 32 + td * 4]) =
                make_float4(acc[j][0], acc[j][1], acc[j][2], acc[j][3]);
        }
        #pragma unroll
        for (int h = 0; h < NHEAD; h++) {
            const float* as = &sA[h * 32 + td * 4];
            const float* ad = &sA[128 + h * 32 + td * 4];
            float ps = acc[j][0] * as[0] + acc[j][1] * as[1] + acc[j][2] * as[2] + acc[j][3] * as[3];
            float pd = acc[j][0] * ad[0] + acc[j][1] * ad[1] + acc[j][2] * ad[2] + acc[j][3] * ad[3];
            ps += __shfl_down_sync(0xffffffffu, ps, 4);
            ps += __shfl_down_sync(0xffffffffu, ps, 2);
            ps += __shfl_down_sync(0xffffffffu, ps, 1);
            pd += __shfl_down_sync(0xffffffffu, pd, 4);
            pd += __shfl_down_sync(0xffffffffu, pd, 2);
            pd += __shfl_down_sync(0xffffffffu, pd, 1);
            if (td == 0 && gn < N) {
                g_asrc[(size_t)gn * 4 + h] = ps;
                g_adst[(size_t)gn * 4 + h] = pd;
            }
        }
    }
}

// ---------------------------------------------------------------------------
// Kernel 2: histogram of dst only
// ---------------------------------------------------------------------------
__global__ void __launch_bounds__(256) k_hist(const int* __restrict__ dst, int E) {
    int e = blockIdx.x * 256 + threadIdx.x;
    if (e < E) atomicAdd(&g_count[__ldg(&dst[e])], 1);
}

// ---------------------------------------------------------------------------
// Scan: exclusive prefix sum of count -> row (3 small kernels)
// ---------------------------------------------------------------------------
__global__ void __launch_bounds__(1024) k_scan_a(int N) {
    __shared__ int warp_sums[32];
    int b = blockIdx.x, t = threadIdx.x;
    int idx = b * 1024 + t;
    int v = (idx < N) ? g_count[idx] : 0;
    int lane = t & 31, w = t >> 5;
    int x = v;
    #pragma unroll
    for (int o = 1; o < 32; o <<= 1) {
        int y = __shfl_up_sync(0xffffffffu, x, o);
        if (lane >= o) x += y;
    }
    if (lane == 31) warp_sums[w] = x;
    __syncthreads();
    if (w == 0) {
        int s = warp_sums[lane];
        #pragma unroll
        for (int o = 1; o < 32; o <<= 1) {
            int y = __shfl_up_sync(0xffffffffu, s, o);
            if (lane >= o) s += y;
        }
        warp_sums[lane] = s;
    }
    __syncthreads();
    int warp_off = (w > 0) ? warp_sums[w - 1] : 0;
    if (idx < N) g_row[idx] = warp_off + x - v;   // exclusive
    if (t == 0) g_bsum[b] = warp_sums[31];        // block total
}

__global__ void __launch_bounds__(256) k_scan_b(int NB) {
    __shared__ int s[256];
    int t = threadIdx.x;
    s[t] = (t < NB) ? g_bsum[t] : 0;
    __syncthreads();
    #pragma unroll
    for (int o = 1; o < 256; o <<= 1) {
        int v = (t >= o) ? s[t - o] : 0;
        __syncthreads();
        s[t] += v;
        __syncthreads();
    }
    if (t < NB) g_bsum[t] = s[t];                 // inclusive
}

__global__ void __launch_bounds__(1024) k_scan_c(int N) {
    int idx = blockIdx.x * 1024 + threadIdx.x;
    if (idx >= N) return;
    int b = idx >> 10;
    int off = (b > 0) ? g_bsum[b - 1] : 0;
    int r = g_row[idx] + off;
    g_row[idx] = r;
    g_cursor[idx] = r;
}

// ---------------------------------------------------------------------------
// Kernel 3 (fused): per-edge exp, denom[src] reduction, packed-record scatter.
// Global max cancels in softmax (denominator eps perturbation ~1e-16) -> skip.
// ---------------------------------------------------------------------------
__global__ void __launch_bounds__(256) k_edge_fused(const int* __restrict__ ei, int E) {
    int e = blockIdx.x * 256 + threadIdx.x;
    if (e >= E) return;
    int s = __ldg(&ei[e]);
    int d = __ldg(&ei[E + e]);
    float4 as = *reinterpret_cast<const float4*>(&g_asrc[(size_t)s * 4]);
    float4 ad = *reinterpret_cast<const float4*>(&g_adst[(size_t)d * 4]);
    float4 ex; float v;
    v = as.x + ad.x; v = v > 0.f ? v : 0.2f * v; ex.x = __expf(v);
    v = as.y + ad.y; v = v > 0.f ? v : 0.2f * v; ex.y = __expf(v);
    v = as.z + ad.z; v = v > 0.f ? v : 0.2f * v; ex.z = __expf(v);
    v = as.w + ad.w; v = v > 0.f ? v : 0.2f * v; ex.w = __expf(v);
    red_add_v4(&g_denom[(size_t)s * 4], ex);
    int pos = atomicAdd(&g_cursor[d], 1);
    Rec r;
    r.a = make_float4(__int_as_float(s), ex.x, ex.y, ex.z);
    r.b = make_float4(ex.w, 0.f, 0.f, 0.f);
    g_csr[pos] = r;                                // 2x STG.128, same 64B line
}

// ---------------------------------------------------------------------------
// Kernel 4: denom -> 1/(denom + eps) in place
// ---------------------------------------------------------------------------
__global__ void __launch_bounds__(256) k_rcp(int N) {
    int i = blockIdx.x * 256 + threadIdx.x;
    if (i >= N) return;
    float4 d = *reinterpret_cast<float4*>(&g_denom[(size_t)i * 4]);
    d.x = 1.f / (d.x + 1e-16f);
    d.y = 1.f / (d.y + 1e-16f);
    d.z = 1.f / (d.z + 1e-16f);
    d.w = 1.f / (d.w + 1e-16f);
    *reinterpret_cast<float4*>(&g_denom[(size_t)i * 4]) = d;
}

// ---------------------------------------------------------------------------
// Kernel 5: gather — warp per dst node, register accumulation, one store.
// lane l: h = l>>3, q = l&7 owns out[node][h*32 + 4q .. 4q+3].
// ---------------------------------------------------------------------------
__device__ __forceinline__ float rec_ex(const Rec& r, int h) {
    float e = r.a.y;
    e = (h == 1) ? r.a.z : e;
    e = (h == 2) ? r.a.w : e;
    e = (h == 3) ? r.b.x : e;
    return e;
}

__global__ void __launch_bounds__(256) k_gather(float* __restrict__ out, int N) {
    int warp = threadIdx.x >> 5;
    int lane = threadIdx.x & 31;
    int node = blockIdx.x * 8 + warp;
    if (node >= N) return;
    int start = __ldg(&g_row[node]);
    int cnt   = __ldg(&g_count[node]);
    int h = lane >> 3, q = lane & 7;

    float4 acc = make_float4(0.f, 0.f, 0.f, 0.f);
    int i = 0;
    for (; i + 4 <= cnt; i += 4) {
        int p = start + i;
        Rec r0 = g_csr[p + 0];
        Rec r1 = g_csr[p + 1];
        Rec r2 = g_csr[p + 2];
        Rec r3 = g_csr[p + 3];
        int s0 = __float_as_int(r0.a.x);
        int s1 = __float_as_int(r1.a.x);
        int s2 = __float_as_int(r2.a.x);
        int s3 = __float_as_int(r3.a.x);
        float a0 = rec_ex(r0, h) * __ldg(&g_denom[(size_t)s0 * 4 + h]);
        float a1 = rec_ex(r1, h) * __ldg(&g_denom[(size_t)s1 * 4 + h]);
        float a2 = rec_ex(r2, h) * __ldg(&g_denom[(size_t)s2 * 4 + h]);
        float a3 = rec_ex(r3, h) * __ldg(&g_denom[(size_t)s3 * 4 + h]);
        float4 w0 = __ldg(reinterpret_cast<const float4*>(&g_Wh[(size_t)s0 * 32 + q * 4]));
        float4 w1 = __ldg(reinterpret_cast<const float4*>(&g_Wh[(size_t)s1 * 32 + q * 4]));
        float4 w2 = __ldg(reinterpret_cast<const float4*>(&g_Wh[(size_t)s2 * 32 + q * 4]));
        float4 w3 = __ldg(reinterpret_cast<const float4*>(&g_Wh[(size_t)s3 * 32 + q * 4]));
        acc.x += a0 * w0.x + a1 * w1.x + a2 * w2.x + a3 * w3.x;
        acc.y += a0 * w0.y + a1 * w1.y + a2 * w2.y + a3 * w3.y;
        acc.z += a0 * w0.z + a1 * w1.z + a2 * w2.z + a3 * w3.z;
        acc.w += a0 * w0.w + a1 * w1.w + a2 * w2.w + a3 * w3.w;
    }
    for (; i < cnt; i++) {
        int p = start + i;
        Rec r0 = g_csr[p];
        int s0 = __float_as_int(r0.a.x);
        float a0 = rec_ex(r0, h) * __ldg(&g_denom[(size_t)s0 * 4 + h]);
        float4 w0 = __ldg(reinterpret_cast<const float4*>(&g_Wh[(size_t)s0 * 32 + q * 4]));
        acc.x += a0 * w0.x; acc.y += a0 * w0.y; acc.z += a0 * w0.z; acc.w += a0 * w0.w;
    }
    *reinterpret_cast<float4*>(&out[(size_t)node * 128 + lane * 4]) = acc;
}

// ---------------------------------------------------------------------------
extern "C" void kernel_launch(void* const* d_in, const int* in_sizes, int n_in,
                              void* d_out, int out_size) {
    const float* feat = (const float*)d_in[0];
    const float* W    = (const float*)d_in[1];
    const float* b    = (const float*)d_in[2];
    const float* attS = (const float*)d_in[3];
    const float* attD = (const float*)d_in[4];
    const int*   ei   = (const int*)d_in[5];
    float* out = (float*)d_out;

    int N = in_sizes[0] / IN_D;
    int E = in_sizes[5] / 2;

    int NB = (N + 1023) / 1024;     // <= 256 for N <= 262144

    k_zero<<<(N + 255) / 256, 256>>>(N);
    k_hist<<<(E + 255) / 256, 256>>>(ei + E, E);
    k_scan_a<<<NB, 1024>>>(N);
    k_proj<<<(N + 31) / 32, 128>>>(feat, W, b, attS, attD, N);   // slot #4 for ncu
    k_scan_b<<<1, 256>>>(NB);
    k_scan_c<<<NB, 1024>>>(N);
    k_edge_fused<<<(E + 255) / 256, 256>>>(ei, E);
    k_rcp<<<(N + 255) / 256, 256>>>(N);
    k_gather<<<(N + 7) / 8, 256>>>(out, N);
}

// round 8
// speedup vs baseline: 1.7990x; 1.0186x over previous
#include <cuda_runtime.h>
#include <cuda_bf16.h>

// Problem constants (fixed by the dataset)
#define NMAX 100001
#define EMAX 1600000
#define IN_D 128
#define OUT_D 32
#define NHEAD 4

struct __align__(32) Rec { float4 a; float4 b; };   // a = {src, ex0, ex1, ex2}, b.x = ex3

// Scratch (allocation-free: __device__ globals)
__device__ float g_Wh[(size_t)NMAX * OUT_D];
__device__ float g_asrc[(size_t)NMAX * NHEAD];
__device__ float g_adst[(size_t)NMAX * NHEAD];
__device__ float g_denom[(size_t)NMAX * NHEAD];     // later overwritten with 1/(denom+eps)
__device__ int   g_count[NMAX];
__device__ int   g_row[NMAX];
__device__ int   g_cursor[NMAX];
__device__ int   g_bsum[256];
__device__ Rec   g_csr[EMAX];                       // 51.2 MB packed records

__device__ __forceinline__ void red_add_v4(float* p, float4 v) {
    asm volatile("red.global.add.v4.f32 [%0], {%1,%2,%3,%4};"
                 :: "l"(p), "f"(v.x), "f"(v.y), "f"(v.z), "f"(v.w) : "memory");
}

// ---------------------------------------------------------------------------
// Kernel 0: zero denom + count
// ---------------------------------------------------------------------------
__global__ void __launch_bounds__(256) k_zero(int N) {
    int i = blockIdx.x * 256 + threadIdx.x;
    if (i < N) {
        *reinterpret_cast<float4*>(&g_denom[(size_t)i * 4]) = make_float4(0.f, 0.f, 0.f, 0.f);
        g_count[i] = 0;
    }
}

// ---------------------------------------------------------------------------
// Kernel 1: Wh = feat @ W^T + b ; a_src/a_dst projections
// 256 threads, 128 nodes/block, 4 nodes x 4 dims per thread.
// Dynamic smem: sW 16384 + sF 67584 (128x132 padded) + sA 1024 = 84992 B.
// ---------------------------------------------------------------------------
#define PROJ_SMEM (16384 + 128 * 132 * 4 + 1024)

__global__ void __launch_bounds__(256) k_proj(
    const float* __restrict__ feat, const float* __restrict__ W,
    const float* __restrict__ bias, const float* __restrict__ attS,
    const float* __restrict__ attD, int N)
{
    extern __shared__ float smem[];
    float* sW = smem;                  // [128 k][32 d] transposed
    float* sF = smem + 4096;           // 128 rows x 132 floats (padded)
    float* sA = smem + 4096 + 128 * 132;

    int tid = threadIdx.x;
    int node0 = blockIdx.x * 128;

    #pragma unroll
    for (int i = 0; i < 16; i++) {
        int idx = tid + i * 256;            // idx = d*128 + k
        int d = idx >> 7, k = idx & 127;
        sW[k * 32 + d] = W[idx];
    }
    sA[tid] = (tid < 128) ? attS[tid] : attD[tid - 128];

    const float4* f4 = reinterpret_cast<const float4*>(feat);
    #pragma unroll
    for (int i = 0; i < 16; i++) {
        int idx = tid + i * 256;            // 0..4095
        int n = idx >> 5, c = idx & 31;
        int gn = node0 + n;
        float4 v = (gn < N) ? f4[(size_t)gn * 32 + c] : make_float4(0.f, 0.f, 0.f, 0.f);
        *reinterpret_cast<float4*>(&sF[n * 132 + c * 4]) = v;
    }
    __syncthreads();

    int td = tid & 7, tn = tid >> 3;        // tn in [0,32): nodes 4tn .. 4tn+3
    float acc[4][4];
    #pragma unroll
    for (int c = 0; c < 4; c++) {
        float bb = __ldg(&bias[td * 4 + c]);
        acc[0][c] = bb; acc[1][c] = bb; acc[2][c] = bb; acc[3][c] = bb;
    }

    #pragma unroll 2
    for (int k4 = 0; k4 < 32; k4++) {
        float4 w0 = *reinterpret_cast<float4*>(&sW[(k4 * 4 + 0) * 32 + td * 4]);
        float4 w1 = *reinterpret_cast<float4*>(&sW[(k4 * 4 + 1) * 32 + td * 4]);
        float4 w2 = *reinterpret_cast<float4*>(&sW[(k4 * 4 + 2) * 32 + td * 4]);
        float4 w3 = *reinterpret_cast<float4*>(&sW[(k4 * 4 + 3) * 32 + td * 4]);
        #pragma unroll
        for (int j = 0; j < 4; j++) {
            float4 f = *reinterpret_cast<float4*>(&sF[(tn * 4 + j) * 132 + k4 * 4]);
            acc[j][0] += f.x * w0.x + f.y * w1.x + f.z * w2.x + f.w * w3.x;
            acc[j][1] += f.x * w0.y + f.y * w1.y + f.z * w2.y + f.w * w3.y;
            acc[j][2] += f.x * w0.z + f.y * w1.z + f.z * w2.z + f.w * w3.z;
            acc[j][3] += f.x * w0.w + f.y * w1.w + f.z * w2.w + f.w * w3.w;
        }
    }

    #pragma unroll
    for (int j = 0; j < 4; j++) {
        int gn = node0 + tn * 4 + j;
        if (gn < N) {
            *reinterpret_cast<float4*>(&g_Wh[(size_t)gn * 32 + td * 4]) =
                make_float4(acc[j][0], acc[j][1], acc[j][2], acc[j][3]);
        }
        #pragma unroll
        for (int h = 0; h < NHEAD; h++) {
            const float* as = &sA[h * 32 + td * 4];
            const float* ad = &sA[128 + h * 32 + td * 4];
            float ps = acc[j][0] * as[0] + acc[j][1] * as[1] + acc[j][2] * as[2] + acc[j][3] * as[3];
            float pd = acc[j][0] * ad[0] + acc[j][1] * ad[1] + acc[j][2] * ad[2] + acc[j][3] * ad[3];
            ps += __shfl_down_sync(0xffffffffu, ps, 4);
            ps += __shfl_down_sync(0xffffffffu, ps, 2);
            ps += __shfl_down_sync(0xffffffffu, ps, 1);
            pd += __shfl_down_sync(0xffffffffu, pd, 4);
            pd += __shfl_down_sync(0xffffffffu, pd, 2);
            pd += __shfl_down_sync(0xffffffffu, pd, 1);
            if (td == 0 && gn < N) {
                g_asrc[(size_t)gn * 4 + h] = ps;
                g_adst[(size_t)gn * 4 + h] = pd;
            }
        }
    }
}

// ---------------------------------------------------------------------------
// Kernel 2: histogram of dst only
// ---------------------------------------------------------------------------
__global__ void __launch_bounds__(256) k_hist(const int* __restrict__ dst, int E) {
    int e = blockIdx.x * 256 + threadIdx.x;
    if (e < E) atomicAdd(&g_count[__ldg(&dst[e])], 1);
}

// ---------------------------------------------------------------------------
// Scan: exclusive prefix sum of count -> row (3 small kernels)
// ---------------------------------------------------------------------------
__global__ void __launch_bounds__(1024) k_scan_a(int N) {
    __shared__ int warp_sums[32];
    int b = blockIdx.x, t = threadIdx.x;
    int idx = b * 1024 + t;
    int v = (idx < N) ? g_count[idx] : 0;
    int lane = t & 31, w = t >> 5;
    int x = v;
    #pragma unroll
    for (int o = 1; o < 32; o <<= 1) {
        int y = __shfl_up_sync(0xffffffffu, x, o);
        if (lane >= o) x += y;
    }
    if (lane == 31) warp_sums[w] = x;
    __syncthreads();
    if (w == 0) {
        int s = warp_sums[lane];
        #pragma unroll
        for (int o = 1; o < 32; o <<= 1) {
            int y = __shfl_up_sync(0xffffffffu, s, o);
            if (lane >= o) s += y;
        }
        warp_sums[lane] = s;
    }
    __syncthreads();
    int warp_off = (w > 0) ? warp_sums[w - 1] : 0;
    if (idx < N) g_row[idx] = warp_off + x - v;   // exclusive
    if (t == 0) g_bsum[b] = warp_sums[31];        // block total
}

__global__ void __launch_bounds__(256) k_scan_b(int NB) {
    __shared__ int s[256];
    int t = threadIdx.x;
    s[t] = (t < NB) ? g_bsum[t] : 0;
    __syncthreads();
    #pragma unroll
    for (int o = 1; o < 256; o <<= 1) {
        int v = (t >= o) ? s[t - o] : 0;
        __syncthreads();
        s[t] += v;
        __syncthreads();
    }
    if (t < NB) g_bsum[t] = s[t];                 // inclusive
}

__global__ void __launch_bounds__(1024) k_scan_c(int N) {
    int idx = blockIdx.x * 1024 + threadIdx.x;
    if (idx >= N) return;
    int b = idx >> 10;
    int off = (b > 0) ? g_bsum[b - 1] : 0;
    int r = g_row[idx] + off;
    g_row[idx] = r;
    g_cursor[idx] = r;
}

// ---------------------------------------------------------------------------
// Kernel 3 (fused): per-edge exp, denom[src] reduction, packed-record scatter.
// Global max cancels in softmax (denominator eps perturbation ~1e-16) -> skip.
// ---------------------------------------------------------------------------
__global__ void __launch_bounds__(256) k_edge_fused(const int* __restrict__ ei, int E) {
    int e = blockIdx.x * 256 + threadIdx.x;
    if (e >= E) return;
    int s = __ldg(&ei[e]);
    int d = __ldg(&ei[E + e]);
    float4 as = *reinterpret_cast<const float4*>(&g_asrc[(size_t)s * 4]);
    float4 ad = *reinterpret_cast<const float4*>(&g_adst[(size_t)d * 4]);
    float4 ex; float v;
    v = as.x + ad.x; v = v > 0.f ? v : 0.2f * v; ex.x = __expf(v);
    v = as.y + ad.y; v = v > 0.f ? v : 0.2f * v; ex.y = __expf(v);
    v = as.z + ad.z; v = v > 0.f ? v : 0.2f * v; ex.z = __expf(v);
    v = as.w + ad.w; v = v > 0.f ? v : 0.2f * v; ex.w = __expf(v);
    red_add_v4(&g_denom[(size_t)s * 4], ex);
    int pos = atomicAdd(&g_cursor[d], 1);
    Rec r;
    r.a = make_float4(__int_as_float(s), ex.x, ex.y, ex.z);
    r.b = make_float4(ex.w, 0.f, 0.f, 0.f);
    g_csr[pos] = r;                                // 2x STG.128, same 64B line
}

// ---------------------------------------------------------------------------
// Kernel 4: denom -> 1/(denom + eps) in place
// ---------------------------------------------------------------------------
__global__ void __launch_bounds__(256) k_rcp(int N) {
    int i = blockIdx.x * 256 + threadIdx.x;
    if (i >= N) return;
    float4 d = *reinterpret_cast<float4*>(&g_denom[(size_t)i * 4]);
    d.x = 1.f / (d.x + 1e-16f);
    d.y = 1.f / (d.y + 1e-16f);
    d.z = 1.f / (d.z + 1e-16f);
    d.w = 1.f / (d.w + 1e-16f);
    *reinterpret_cast<float4*>(&g_denom[(size_t)i * 4]) = d;
}

// ---------------------------------------------------------------------------
// Kernel 5: gather — warp per dst node, register accumulation, one store.
// lane l: h = l>>3, q = l&7 owns out[node][h*32 + 4q .. 4q+3].
// ---------------------------------------------------------------------------
__device__ __forceinline__ float rec_ex(const Rec& r, int h) {
    float e = r.a.y;
    e = (h == 1) ? r.a.z : e;
    e = (h == 2) ? r.a.w : e;
    e = (h == 3) ? r.b.x : e;
    return e;
}

__global__ void __launch_bounds__(256) k_gather(float* __restrict__ out, int N) {
    int warp = threadIdx.x >> 5;
    int lane = threadIdx.x & 31;
    int node = blockIdx.x * 8 + warp;
    if (node >= N) return;
    int start = __ldg(&g_row[node]);
    int cnt   = __ldg(&g_count[node]);
    int h = lane >> 3, q = lane & 7;

    float4 acc = make_float4(0.f, 0.f, 0.f, 0.f);
    int i = 0;
    for (; i + 4 <= cnt; i += 4) {
        int p = start + i;
        Rec r0 = g_csr[p + 0];
        Rec r1 = g_csr[p + 1];
        Rec r2 = g_csr[p + 2];
        Rec r3 = g_csr[p + 3];
        int s0 = __float_as_int(r0.a.x);
        int s1 = __float_as_int(r1.a.x);
        int s2 = __float_as_int(r2.a.x);
        int s3 = __float_as_int(r3.a.x);
        float a0 = rec_ex(r0, h) * __ldg(&g_denom[(size_t)s0 * 4 + h]);
        float a1 = rec_ex(r1, h) * __ldg(&g_denom[(size_t)s1 * 4 + h]);
        float a2 = rec_ex(r2, h) * __ldg(&g_denom[(size_t)s2 * 4 + h]);
        float a3 = rec_ex(r3, h) * __ldg(&g_denom[(size_t)s3 * 4 + h]);
        float4 w0 = __ldg(reinterpret_cast<const float4*>(&g_Wh[(size_t)s0 * 32 + q * 4]));
        float4 w1 = __ldg(reinterpret_cast<const float4*>(&g_Wh[(size_t)s1 * 32 + q * 4]));
        float4 w2 = __ldg(reinterpret_cast<const float4*>(&g_Wh[(size_t)s2 * 32 + q * 4]));
        float4 w3 = __ldg(reinterpret_cast<const float4*>(&g_Wh[(size_t)s3 * 32 + q * 4]));
        acc.x += a0 * w0.x + a1 * w1.x + a2 * w2.x + a3 * w3.x;
        acc.y += a0 * w0.y + a1 * w1.y + a2 * w2.y + a3 * w3.y;
        acc.z += a0 * w0.z + a1 * w1.z + a2 * w2.z + a3 * w3.z;
        acc.w += a0 * w0.w + a1 * w1.w + a2 * w2.w + a3 * w3.w;
    }
    for (; i < cnt; i++) {
        int p = start + i;
        Rec r0 = g_csr[p];
        int s0 = __float_as_int(r0.a.x);
        float a0 = rec_ex(r0, h) * __ldg(&g_denom[(size_t)s0 * 4 + h]);
        float4 w0 = __ldg(reinterpret_cast<const float4*>(&g_Wh[(size_t)s0 * 32 + q * 4]));
        acc.x += a0 * w0.x; acc.y += a0 * w0.y; acc.z += a0 * w0.z; acc.w += a0 * w0.w;
    }
    *reinterpret_cast<float4*>(&out[(size_t)node * 128 + lane * 4]) = acc;
}

// ---------------------------------------------------------------------------
extern "C" void kernel_launch(void* const* d_in, const int* in_sizes, int n_in,
                              void* d_out, int out_size) {
    const float* feat = (const float*)d_in[0];
    const float* W    = (const float*)d_in[1];
    const float* b    = (const float*)d_in[2];
    const float* attS = (const float*)d_in[3];
    const float* attD = (const float*)d_in[4];
    const int*   ei   = (const int*)d_in[5];
    float* out = (float*)d_out;

    int N = in_sizes[0] / IN_D;
    int E = in_sizes[5] / 2;

    int NB = (N + 1023) / 1024;     // <= 256 for N <= 262144

    // Opt-in to >48KB dynamic smem for k_proj (idempotent; not a stream op)
    cudaFuncSetAttribute(k_proj, cudaFuncAttributeMaxDynamicSharedMemorySize, PROJ_SMEM);

    k_zero<<<(N + 255) / 256, 256>>>(N);
    k_hist<<<(E + 255) / 256, 256>>>(ei + E, E);
    k_scan_a<<<NB, 1024>>>(N);
    k_proj<<<(N + 127) / 128, 256, PROJ_SMEM>>>(feat, W, b, attS, attD, N);  // slot #3 for ncu
    k_scan_b<<<1, 256>>>(NB);
    k_scan_c<<<NB, 1024>>>(N);
    k_edge_fused<<<(E + 255) / 256, 256>>>(ei, E);
    k_rcp<<<(N + 255) / 256, 256>>>(N);
    k_gather<<<(N + 7) / 8, 256>>>(out, N);
}

// round 9
// speedup vs baseline: 1.9893x; 1.1058x over previous
#include <cuda_runtime.h>
#include <cuda_fp16.h>

// Problem constants (fixed by the dataset)
#define NMAX 100001
#define EMAX 1600000
#define IN_D 128
#define OUT_D 32
#define NHEAD 4

// Scratch (allocation-free: __device__ globals)
__device__ float g_Wh[(size_t)NMAX * OUT_D];
__device__ float g_asrc[(size_t)NMAX * NHEAD];
__device__ float g_adst[(size_t)NMAX * NHEAD];
__device__ float g_denom[(size_t)NMAX * NHEAD];     // later overwritten with 1/(denom+eps)
__device__ int   g_count[NMAX];
__device__ int   g_row[NMAX];
__device__ int   g_cursor[NMAX];
__device__ int   g_bsum[256];
__device__ float4 g_csr[EMAX];                      // 25.6 MB: {src, ex01(h2), ex23(h2), unused}

__device__ __forceinline__ void red_add_v4(float* p, float4 v) {
    asm volatile("red.global.add.v4.f32 [%0], {%1,%2,%3,%4};"
                 :: "l"(p), "f"(v.x), "f"(v.y), "f"(v.z), "f"(v.w) : "memory");
}

// ---------------------------------------------------------------------------
// Kernel 0: zero denom + count
// ---------------------------------------------------------------------------
__global__ void __launch_bounds__(256) k_zero(int N) {
    int i = blockIdx.x * 256 + threadIdx.x;
    if (i < N) {
        *reinterpret_cast<float4*>(&g_denom[(size_t)i * 4]) = make_float4(0.f, 0.f, 0.f, 0.f);
        g_count[i] = 0;
    }
}

// ---------------------------------------------------------------------------
// Kernel 1: Wh = feat @ W^T + b ; a_src/a_dst projections
// 256 threads, 128 nodes/block, 4 nodes x 4 dims per thread.
// Dynamic smem: sW 16384 + sF 67584 (128x132 padded) + sA 1024 = 84992 B.
// ---------------------------------------------------------------------------
#define PROJ_SMEM (16384 + 128 * 132 * 4 + 1024)

__global__ void __launch_bounds__(256) k_proj(
    const float* __restrict__ feat, const float* __restrict__ W,
    const float* __restrict__ bias, const float* __restrict__ attS,
    const float* __restrict__ attD, int N)
{
    extern __shared__ float smem[];
    float* sW = smem;                  // [128 k][32 d] transposed
    float* sF = smem + 4096;           // 128 rows x 132 floats (padded)
    float* sA = smem + 4096 + 128 * 132;

    int tid = threadIdx.x;
    int node0 = blockIdx.x * 128;

    #pragma unroll
    for (int i = 0; i < 16; i++) {
        int idx = tid + i * 256;            // idx = d*128 + k
        int d = idx >> 7, k = idx & 127;
        sW[k * 32 + d] = W[idx];
    }
    sA[tid] = (tid < 128) ? attS[tid] : attD[tid - 128];

    const float4* f4 = reinterpret_cast<const float4*>(feat);
    #pragma unroll
    for (int i = 0; i < 16; i++) {
        int idx = tid + i * 256;            // 0..4095
        int n = idx >> 5, c = idx & 31;
        int gn = node0 + n;
        float4 v = (gn < N) ? f4[(size_t)gn * 32 + c] : make_float4(0.f, 0.f, 0.f, 0.f);
        *reinterpret_cast<float4*>(&sF[n * 132 + c * 4]) = v;
    }
    __syncthreads();

    int td = tid & 7, tn = tid >> 3;        // tn in [0,32): nodes 4tn .. 4tn+3
    float acc[4][4];
    #pragma unroll
    for (int c = 0; c < 4; c++) {
        float bb = __ldg(&bias[td * 4 + c]);
        acc[0][c] = bb; acc[1][c] = bb; acc[2][c] = bb; acc[3][c] = bb;
    }

    #pragma unroll 2
    for (int k4 = 0; k4 < 32; k4++) {
        float4 w0 = *reinterpret_cast<float4*>(&sW[(k4 * 4 + 0) * 32 + td * 4]);
        float4 w1 = *reinterpret_cast<float4*>(&sW[(k4 * 4 + 1) * 32 + td * 4]);
        float4 w2 = *reinterpret_cast<float4*>(&sW[(k4 * 4 + 2) * 32 + td * 4]);
        float4 w3 = *reinterpret_cast<float4*>(&sW[(k4 * 4 + 3) * 32 + td * 4]);
        #pragma unroll
        for (int j = 0; j < 4; j++) {
            float4 f = *reinterpret_cast<float4*>(&sF[(tn * 4 + j) * 132 + k4 * 4]);
            acc[j][0] += f.x * w0.x + f.y * w1.x + f.z * w2.x + f.w * w3.x;
            acc[j][1] += f.x * w0.y + f.y * w1.y + f.z * w2.y + f.w * w3.y;
            acc[j][2] += f.x * w0.z + f.y * w1.z + f.z * w2.z + f.w * w3.z;
            acc[j][3] += f.x * w0.w + f.y * w1.w + f.z * w2.w + f.w * w3.w;
        }
    }

    #pragma unroll
    for (int j = 0; j < 4; j++) {
        int gn = node0 + tn * 4 + j;
        if (gn < N) {
            *reinterpret_cast<float4*>(&g_Wh[(size_t)gn * 32 + td * 4]) =
                make_float4(acc[j][0], acc[j][1], acc[j][2], acc[j][3]);
        }
        #pragma unroll
        for (int h = 0; h < NHEAD; h++) {
            const float* as = &sA[h * 32 + td * 4];
            const float* ad = &sA[128 + h * 32 + td * 4];
            float ps = acc[j][0] * as[0] + acc[j][1] * as[1] + acc[j][2] * as[2] + acc[j][3] * as[3];
            float pd = acc[j][0] * ad[0] + acc[j][1] * ad[1] + acc[j][2] * ad[2] + acc[j][3] * ad[3];
            ps += __shfl_down_sync(0xffffffffu, ps, 4);
            ps += __shfl_down_sync(0xffffffffu, ps, 2);
            ps += __shfl_down_sync(0xffffffffu, ps, 1);
            pd += __shfl_down_sync(0xffffffffu, pd, 4);
            pd += __shfl_down_sync(0xffffffffu, pd, 2);
            pd += __shfl_down_sync(0xffffffffu, pd, 1);
            if (td == 0 && gn < N) {
                g_asrc[(size_t)gn * 4 + h] = ps;
                g_adst[(size_t)gn * 4 + h] = pd;
            }
        }
    }
}

// ---------------------------------------------------------------------------
// Kernel 2: histogram of dst only
// ---------------------------------------------------------------------------
__global__ void __launch_bounds__(256) k_hist(const int* __restrict__ dst, int E) {
    int e = blockIdx.x * 256 + threadIdx.x;
    if (e < E) atomicAdd(&g_count[__ldg(&dst[e])], 1);
}

// ---------------------------------------------------------------------------
// Scan: exclusive prefix sum of count -> row (3 small kernels)
// ---------------------------------------------------------------------------
__global__ void __launch_bounds__(1024) k_scan_a(int N) {
    __shared__ int warp_sums[32];
    int b = blockIdx.x, t = threadIdx.x;
    int idx = b * 1024 + t;
    int v = (idx < N) ? g_count[idx] : 0;
    int lane = t & 31, w = t >> 5;
    int x = v;
    #pragma unroll
    for (int o = 1; o < 32; o <<= 1) {
        int y = __shfl_up_sync(0xffffffffu, x, o);
        if (lane >= o) x += y;
    }
    if (lane == 31) warp_sums[w] = x;
    __syncthreads();
    if (w == 0) {
        int s = warp_sums[lane];
        #pragma unroll
        for (int o = 1; o < 32; o <<= 1) {
            int y = __shfl_up_sync(0xffffffffu, s, o);
            if (lane >= o) s += y;
        }
        warp_sums[lane] = s;
    }
    __syncthreads();
    int warp_off = (w > 0) ? warp_sums[w - 1] : 0;
    if (idx < N) g_row[idx] = warp_off + x - v;   // exclusive
    if (t == 0) g_bsum[b] = warp_sums[31];        // block total
}

__global__ void __launch_bounds__(256) k_scan_b(int NB) {
    __shared__ int s[256];
    int t = threadIdx.x;
    s[t] = (t < NB) ? g_bsum[t] : 0;
    __syncthreads();
    #pragma unroll
    for (int o = 1; o < 256; o <<= 1) {
        int v = (t >= o) ? s[t - o] : 0;
        __syncthreads();
        s[t] += v;
        __syncthreads();
    }
    if (t < NB) g_bsum[t] = s[t];                 // inclusive
}

__global__ void __launch_bounds__(1024) k_scan_c(int N) {
    int idx = blockIdx.x * 1024 + threadIdx.x;
    if (idx >= N) return;
    int b = idx >> 10;
    int off = (b > 0) ? g_bsum[b - 1] : 0;
    int r = g_row[idx] + off;
    g_row[idx] = r;
    g_cursor[idx] = r;
}

// ---------------------------------------------------------------------------
// Kernel 3 (fused): per-edge exp, denom[src] reduction, 16B-record scatter.
// Global max cancels in softmax (denominator eps perturbation ~1e-16) -> skip.
// Record: {src:int, ex01:half2, ex23:half2, pad} as one float4.
// ---------------------------------------------------------------------------
__global__ void __launch_bounds__(256) k_edge_fused(const int* __restrict__ ei, int E) {
    int e = blockIdx.x * 256 + threadIdx.x;
    if (e >= E) return;
    int s = __ldg(&ei[e]);
    int d = __ldg(&ei[E + e]);
    float4 as = *reinterpret_cast<const float4*>(&g_asrc[(size_t)s * 4]);
    float4 ad = *reinterpret_cast<const float4*>(&g_adst[(size_t)d * 4]);
    float4 ex; float v;
    v = as.x + ad.x; v = v > 0.f ? v : 0.2f * v; ex.x = __expf(v);
    v = as.y + ad.y; v = v > 0.f ? v : 0.2f * v; ex.y = __expf(v);
    v = as.z + ad.z; v = v > 0.f ? v : 0.2f * v; ex.z = __expf(v);
    v = as.w + ad.w; v = v > 0.f ? v : 0.2f * v; ex.w = __expf(v);
    red_add_v4(&g_denom[(size_t)s * 4], ex);
    int pos = atomicAdd(&g_cursor[d], 1);
    __half2 h01 = __floats2half2_rn(ex.x, ex.y);
    __half2 h23 = __floats2half2_rn(ex.z, ex.w);
    float4 r;
    r.x = __int_as_float(s);
    r.y = __uint_as_float(*reinterpret_cast<unsigned*>(&h01));
    r.z = __uint_as_float(*reinterpret_cast<unsigned*>(&h23));
    r.w = 0.f;
    g_csr[pos] = r;                                // single STG.128
}

// ---------------------------------------------------------------------------
// Kernel 4: denom -> 1/(denom + eps) in place
// ---------------------------------------------------------------------------
__global__ void __launch_bounds__(256) k_rcp(int N) {
    int i = blockIdx.x * 256 + threadIdx.x;
    if (i >= N) return;
    float4 d = *reinterpret_cast<float4*>(&g_denom[(size_t)i * 4]);
    d.x = 1.f / (d.x + 1e-16f);
    d.y = 1.f / (d.y + 1e-16f);
    d.z = 1.f / (d.z + 1e-16f);
    d.w = 1.f / (d.w + 1e-16f);
    *reinterpret_cast<float4*>(&g_denom[(size_t)i * 4]) = d;
}

// ---------------------------------------------------------------------------
// Kernel 5: gather — warp per dst node, register accumulation, one store.
// lane l: h = l>>3, q = l&7 owns out[node][h*32 + 4q .. 4q+3].
// ---------------------------------------------------------------------------
__device__ __forceinline__ float rec_ex(float4 r, int h) {
    unsigned u01 = __float_as_uint(r.y);
    unsigned u23 = __float_as_uint(r.z);
    __half2 h01 = *reinterpret_cast<__half2*>(&u01);
    __half2 h23 = *reinterpret_cast<__half2*>(&u23);
    float2 f01 = __half22float2(h01);
    float2 f23 = __half22float2(h23);
    float e = f01.x;
    e = (h == 1) ? f01.y : e;
    e = (h == 2) ? f23.x : e;
    e = (h == 3) ? f23.y : e;
    return e;
}

__global__ void __launch_bounds__(256) k_gather(float* __restrict__ out, int N) {
    int warp = threadIdx.x >> 5;
    int lane = threadIdx.x & 31;
    int node = blockIdx.x * 8 + warp;
    if (node >= N) return;
    int start = __ldg(&g_row[node]);
    int cnt   = __ldg(&g_count[node]);
    int h = lane >> 3, q = lane & 7;

    float4 acc = make_float4(0.f, 0.f, 0.f, 0.f);
    int i = 0;
    for (; i + 8 <= cnt; i += 8) {
        int p = start + i;
        float4 r[8];
        #pragma unroll
        for (int u = 0; u < 8; u++) r[u] = __ldg(&g_csr[p + u]);
        int sidx[8];
        #pragma unroll
        for (int u = 0; u < 8; u++) sidx[u] = __float_as_int(r[u].x);
        float4 w[8];
        #pragma unroll
        for (int u = 0; u < 8; u++)
            w[u] = __ldg(reinterpret_cast<const float4*>(&g_Wh[(size_t)sidx[u] * 32 + q * 4]));
        float a[8];
        #pragma unroll
        for (int u = 0; u < 8; u++)
            a[u] = rec_ex(r[u], h) * __ldg(&g_denom[(size_t)sidx[u] * 4 + h]);
        #pragma unroll
        for (int u = 0; u < 8; u++) {
            acc.x += a[u] * w[u].x;
            acc.y += a[u] * w[u].y;
            acc.z += a[u] * w[u].z;
            acc.w += a[u] * w[u].w;
        }
    }
    for (; i < cnt; i++) {
        int p = start + i;
        float4 r0 = __ldg(&g_csr[p]);
        int s0 = __float_as_int(r0.x);
        float a0 = rec_ex(r0, h) * __ldg(&g_denom[(size_t)s0 * 4 + h]);
        float4 w0 = __ldg(reinterpret_cast<const float4*>(&g_Wh[(size_t)s0 * 32 + q * 4]));
        acc.x += a0 * w0.x; acc.y += a0 * w0.y; acc.z += a0 * w0.z; acc.w += a0 * w0.w;
    }
    *reinterpret_cast<float4*>(&out[(size_t)node * 128 + lane * 4]) = acc;
}

// ---------------------------------------------------------------------------
extern "C" void kernel_launch(void* const* d_in, const int* in_sizes, int n_in,
                              void* d_out, int out_size) {
    const float* feat = (const float*)d_in[0];
    const float* W    = (const float*)d_in[1];
    const float* b    = (const float*)d_in[2];
    const float* attS = (const float*)d_in[3];
    const float* attD = (const float*)d_in[4];
    const int*   ei   = (const int*)d_in[5];
    float* out = (float*)d_out;

    int N = in_sizes[0] / IN_D;
    int E = in_sizes[5] / 2;

    int NB = (N + 1023) / 1024;     // <= 256 for N <= 262144

    // Opt-in to >48KB dynamic smem for k_proj (idempotent; not a stream op)
    cudaFuncSetAttribute(k_proj, cudaFuncAttributeMaxDynamicSharedMemorySize, PROJ_SMEM);

    k_zero<<<(N + 255) / 256, 256>>>(N);
    k_hist<<<(E + 255) / 256, 256>>>(ei + E, E);
    k_scan_a<<<NB, 1024>>>(N);
    k_proj<<<(N + 127) / 128, 256, PROJ_SMEM>>>(feat, W, b, attS, attD, N);  // slot #3 for ncu
    k_scan_b<<<1, 256>>>(NB);
    k_scan_c<<<NB, 1024>>>(N);
    k_edge_fused<<<(E + 255) / 256, 256>>>(ei, E);
    k_rcp<<<(N + 255) / 256, 256>>>(N);
    k_gather<<<(N + 7) / 8, 256>>>(out, N);
}